// round 14
// baseline (speedup 1.0000x reference)
#include <cuda_runtime.h>
#include <cuda_bf16.h>
#include <math.h>
#include <stdint.h>

// Problem constants: B=1, C=256, H=W=96
#define C_DIM 256
#define HDIM  96
#define HW    9216          // H*W
#define CW    24576         // C*W
#define NPIX  (C_DIM*HW)    // 2359296

// ---------------------------------------------------------------------------
// Device-global scratch. bf16 split hi/lo, packed bf16x2 (uint32).
// X / FQ stored TRANSPOSED: [p][c/2] so GEMM B-fragments stage as uint4 copies.
__device__ float    g_FQ[NPIX];                     // fp32 FQ [ch][p]
__device__ uint32_t g_Xth[NPIX/2],  g_Xtl[NPIX/2];  // fuse^T hi/lo [p][c/2]
__device__ uint32_t g_FQth[NPIX/2], g_FQtl[NPIX/2]; // FQ^T   hi/lo [p][c/2]
__device__ uint32_t g_Wh0[32768], g_Wl0[32768];     // Wq hi/lo [o][c/2]
__device__ uint32_t g_Wh1[32768], g_Wl1[32768];     // Wv hi/lo [o][c/2]
__device__ float    g_FQM[CW];                      // Fuse_Q_mask

// ---------------------------------------------------------------------------
__device__ __forceinline__ void atomicMaxFloat(float* addr, float val) {
    if (val >= 0.0f) atomicMax((int*)addr, __float_as_int(val));
    else             atomicMin((unsigned int*)addr, __float_as_uint(val));
}

__device__ __forceinline__ uint32_t pack_bf2(float a, float b) {
    __nv_bfloat16 ha = __float2bfloat16_rn(a);
    __nv_bfloat16 hb = __float2bfloat16_rn(b);
    unsigned short ua = *reinterpret_cast<unsigned short*>(&ha);
    unsigned short ub = *reinterpret_cast<unsigned short*>(&hb);
    return (uint32_t)ua | ((uint32_t)ub << 16);
}
__device__ __forceinline__ float bf_hi_val(float a) {
    __nv_bfloat16 h = __float2bfloat16_rn(a);
    return __bfloat162float(h);
}

// m16n8k16 bf16 MMA, fp32 accumulate (standard PTX, compiles on plain sm_103)
__device__ __forceinline__ void mma16816(float* d, const uint32_t* a,
                                         const uint32_t* b) {
    asm volatile(
        "mma.sync.aligned.m16n8k16.row.col.f32.bf16.bf16.f32 "
        "{%0,%1,%2,%3}, {%4,%5,%6,%7}, {%8,%9}, {%0,%1,%2,%3};"
        : "+f"(d[0]), "+f"(d[1]), "+f"(d[2]), "+f"(d[3])
        : "r"(a[0]), "r"(a[1]), "r"(a[2]), "r"(a[3]), "r"(b[0]), "r"(b[1]));
}

// ---------------------------------------------------------------------------
// Convert Wq, Wv to split bf16 hi/lo (row-major [o][c/2], no transpose).
__global__ __launch_bounds__(256) void convert_w(
    const float* __restrict__ Wq, const float* __restrict__ Wv)
{
    unsigned v = blockIdx.x * 256u + threadIdx.x;   // float4 index
    const float* src; uint32_t *dh, *dl; unsigned base;
    if (v < 16384)      { src = Wq; dh = g_Wh0; dl = g_Wl0; base = v; }
    else if (v < 32768) { src = Wv; dh = g_Wh1; dl = g_Wl1; base = v - 16384; }
    else return;
    float4 x = ((const float4*)src)[base];
    float h0 = bf_hi_val(x.x), h1 = bf_hi_val(x.y);
    float h2 = bf_hi_val(x.z), h3 = bf_hi_val(x.w);
    dh[2*base]   = pack_bf2(x.x, x.y);
    dh[2*base+1] = pack_bf2(x.z, x.w);
    dl[2*base]   = pack_bf2(x.x - h0, x.y - h1);
    dl[2*base+1] = pack_bf2(x.z - h2, x.w - h3);
}

// ---------------------------------------------------------------------------
// Transpose + split-convert: src fp32 [256][9216] -> dh/dl u32 [9216][128],
// each u32 = (bf16(src[2cw][p]), bf16(src[2cw+1][p])). Tile 32c x 64p.
// SRC=0: src = xin (fuse, harness ptr), dest = g_Xth/g_Xtl.
// SRC=1: src = g_FQ (device global, bound IN DEVICE CODE), dest = g_FQth/tl.
template <int SRC>
__global__ __launch_bounds__(256) void transpose_convert(
    const float* __restrict__ xin)
{
    const float* src = (SRC == 0) ? xin : (const float*)g_FQ;
    uint32_t* dh = (SRC == 0) ? g_Xth : g_FQth;
    uint32_t* dl = (SRC == 0) ? g_Xtl : g_FQtl;

    __shared__ float ts[32][65];
    const int p0 = blockIdx.x * 64;
    const int c0 = blockIdx.y * 32;
    const int tid = threadIdx.x;
    #pragma unroll
    for (int k = 0; k < 8; k++) {
        int idx = k * 256 + tid;
        int c = idx >> 6, p = idx & 63;
        ts[c][p] = src[(size_t)(c0 + c) * HW + p0 + p];
    }
    __syncthreads();
    #pragma unroll
    for (int k = 0; k < 4; k++) {
        int idx = k * 256 + tid;
        int p = idx >> 4, cw = idx & 15;
        float a = ts[2*cw][p], b = ts[2*cw + 1][p];
        float ah = bf_hi_val(a), bh = bf_hi_val(b);
        size_t o = (size_t)(p0 + p) * 128 + (c0 >> 1) + cw;
        dh[o] = pack_bf2(a, b);
        dl[o] = pack_bf2(a - ah, b - bh);
    }
}

// ---------------------------------------------------------------------------
// Per-channel frequency filter, latency-optimized: 512 threads, float4 loads
// (high MLP), 4-way-parallel stage 1, vectorized synthesis stores.
// Keep DFT freqs kr,kc in {-2..1}, inverse-synthesize, abs, /9216 -> g_FQ.
__global__ __launch_bounds__(512) void freq_kernel(const float* __restrict__ x) {
    __shared__ float sa[HW];                  // 36864 B
    __shared__ float twc[96], tws[96];
    __shared__ unsigned char pidx[4][96];
    __shared__ float Gp[4][4][96][2];         // (h-quarter, kr, w, re/im)
    __shared__ float s2p[64][2];
    __shared__ float sF[32];
    __shared__ float sP[4][96][2];
    __shared__ float sMin[16], sMax[16];

    const int ch  = blockIdx.x;
    const int tid = threadIdx.x;

    if (ch < 48) g_FQM[ch * 512 + tid] = -INFINITY;   // init Fuse_Q_mask buffer

    if (tid < 96) {  // twiddles, fp64 trig
        double th = 2.0 * 3.14159265358979323846 * (double)tid / 96.0;
        twc[tid] = (float)cos(th);
        tws[tid] = (float)sin(th);
    }
    if (tid >= 128 && tid < 512) {            // phase index table (384 entries)
        int t = tid - 128;
        int k = t / 96, v = t - k * 96;
        int m = ((k - 2) * v) % 96; if (m < 0) m += 96;
        pidx[k][v] = (unsigned char)m;
    }

    // ---- vectorized |x| load: 2304 float4s, 4.5 per thread, high MLP ------
    const float4* xc4 = (const float4*)(x + (size_t)ch * HW);
    float lmin = INFINITY, lmax = -INFINITY;
    #pragma unroll
    for (int k = 0; k < 5; k++) {
        int i = k * 512 + tid;
        if (i < 2304) {
            float4 v = xc4[i];
            float a0 = fabsf(v.x), a1 = fabsf(v.y);
            float a2 = fabsf(v.z), a3 = fabsf(v.w);
            ((float4*)sa)[i] = make_float4(a0, a1, a2, a3);
            lmin = fminf(lmin, fminf(fminf(a0, a1), fminf(a2, a3)));
            lmax = fmaxf(lmax, fmaxf(fmaxf(a0, a1), fmaxf(a2, a3)));
        }
    }
    #pragma unroll
    for (int off = 16; off; off >>= 1) {
        lmin = fminf(lmin, __shfl_down_sync(0xffffffffu, lmin, off));
        lmax = fmaxf(lmax, __shfl_down_sync(0xffffffffu, lmax, off));
    }
    const int wid = tid >> 5, lane = tid & 31;
    if (lane == 0) { sMin[wid] = lmin; sMax[wid] = lmax; }
    __syncthreads();

    float mn = sMin[0], mx = sMax[0];
    #pragma unroll
    for (int j = 1; j < 16; j++) { mn = fminf(mn, sMin[j]); mx = fmaxf(mx, sMax[j]); }
    const float ptp = mx - mn;

    // ---- stage 1: column DFT over h, 4 h-quarters in parallel -------------
    if (tid < 384) {
        const int w  = tid >> 2;
        const int qh = tid & 3;
        const int h0 = qh * 24;
        float gr[4] = {0.f, 0.f, 0.f, 0.f};
        float gi[4] = {0.f, 0.f, 0.f, 0.f};
        for (int j = 0; j < 24; j++) {
            int h = h0 + j;
            float q = floorf(__fdiv_rn(255.0f * (sa[h * 96 + w] - mn), ptp));
            #pragma unroll
            for (int kr = 0; kr < 4; kr++) {
                int m = pidx[kr][h];
                gr[kr] += q * twc[m];
                gi[kr] -= q * tws[m];
            }
        }
        #pragma unroll
        for (int kr = 0; kr < 4; kr++) {
            Gp[qh][kr][w][0] = gr[kr];
            Gp[qh][kr][w][1] = gi[kr];
        }
    }
    __syncthreads();

    // ---- stage 2: 16 coefficients, 64-way parallel then 4:1 combine -------
    if (tid < 64) {
        int coef = tid >> 2, q4 = tid & 3;
        int kr = coef >> 2, kc = coef & 3;
        float fr = 0.f, fi = 0.f;
        int w0 = q4 * 24;
        for (int w = w0; w < w0 + 24; w++) {
            float grw = Gp[0][kr][w][0] + Gp[1][kr][w][0]
                      + Gp[2][kr][w][0] + Gp[3][kr][w][0];
            float giw = Gp[0][kr][w][1] + Gp[1][kr][w][1]
                      + Gp[2][kr][w][1] + Gp[3][kr][w][1];
            int m = pidx[kc][w];
            float cc = twc[m], ss = tws[m];
            fr += grw * cc + giw * ss;
            fi += giw * cc - grw * ss;
        }
        s2p[tid][0] = fr;
        s2p[tid][1] = fi;
    }
    __syncthreads();
    if (tid < 32) {
        int coef = tid >> 1, ri = tid & 1;
        sF[coef * 2 + ri] = s2p[coef * 4][ri] + s2p[coef * 4 + 1][ri]
                          + s2p[coef * 4 + 2][ri] + s2p[coef * 4 + 3][ri];
    }
    __syncthreads();

    // ---- synthesis: column partials over kc -------------------------------
    if (tid < 96) {
        int w = tid;
        #pragma unroll
        for (int kr = 0; kr < 4; kr++) {
            float pre = 0.f, pim = 0.f;
            #pragma unroll
            for (int kc = 0; kc < 4; kc++) {
                int m = pidx[kc][w];
                float fr = sF[2 * (kr * 4 + kc)], fi = sF[2 * (kr * 4 + kc) + 1];
                float cc = twc[m], ss = tws[m];
                pre += fr * cc - fi * ss;
                pim += fr * ss + fi * cc;
            }
            sP[kr][w][0] = pre;
            sP[kr][w][1] = pim;
        }
    }
    __syncthreads();

    // ---- per-pixel inverse + abs, 4 pixels / thread, float4 stores --------
    const float inv = 1.0f / 9216.0f;
    float4* fq4 = (float4*)(g_FQ + (size_t)ch * HW);
    #pragma unroll
    for (int k = 0; k < 5; k++) {
        int i4 = k * 512 + tid;
        if (i4 < 2304) {
            int pix = i4 * 4;
            int h = pix / 96, w0 = pix - h * 96;   // 4 pixels share one row
            float cr[4], sr[4];
            #pragma unroll
            for (int kr = 0; kr < 4; kr++) {
                int m = pidx[kr][h];
                cr[kr] = twc[m]; sr[kr] = tws[m];
            }
            float vv[4];
            #pragma unroll
            for (int dw = 0; dw < 4; dw++) {
                float re = 0.f, im = 0.f;
                #pragma unroll
                for (int kr = 0; kr < 4; kr++) {
                    float pre = sP[kr][w0 + dw][0], pim = sP[kr][w0 + dw][1];
                    re += pre * cr[kr] - pim * sr[kr];
                    im += pre * sr[kr] + pim * cr[kr];
                }
                vv[dw] = sqrtf(re * re + im * im) * inv;
            }
            fq4[i4] = make_float4(vv[0], vv[1], vv[2], vv[3]);
        }
    }
}

// ---------------------------------------------------------------------------
// Split-precision bf16 GEMM via mma.sync.m16n8k16 (HMMA tensor pipe).
// out[o,p] = sum_c W[o,c] X[c,p] + bias[o],  O=256, P=9216, K=256.
// CTA tile: M=128 x N=64, K staged in 4 phases of 64. 55 KB smem -> 2 CTA/SM.
// 8 warps as 2m x 4n (warp tile 64x16). 3 passes: Ah*Bh + Ah*Bl + Al*Bh.
// MODE 0 (Q): X = FQ^T, epilogue class-max into g_FQM.
// MODE 1 (V): X = fuse^T, writes raw (acc+bias) to out.
#define APITCH 36            // u32 per smem row (72 bf16; 36%32=4 -> no conflicts)
#define AH_OFF 0
#define AL_OFF 4608          // 128*36
#define BH_OFF 9216
#define BL_OFF 11520         // +64*36
#define SMEM_U32 13824       // 55296 bytes

template <int MODE>
__global__ __launch_bounds__(256, 2) void gemm_mma(
    const float* __restrict__ bias, float* __restrict__ out)
{
    extern __shared__ uint32_t su[];
    const int tid  = threadIdx.x;
    const int wid  = tid >> 5, lane = tid & 31;
    const int mw   = wid >> 2, nw = wid & 3;     // 2m x 4n warp grid
    const int gq   = lane >> 2, l4 = lane & 3;   // groupID, threadID-in-group
    const int p0   = blockIdx.x * 64;
    const int o0   = blockIdx.y * 128;

    const uint32_t* Ah = (MODE == 0) ? g_Wh0  : g_Wh1;
    const uint32_t* Al = (MODE == 0) ? g_Wl0  : g_Wl1;
    const uint32_t* Xh = (MODE == 0) ? g_FQth : g_Xth;
    const uint32_t* Xl = (MODE == 0) ? g_FQtl : g_Xtl;

    float acc[4][2][4];
    #pragma unroll
    for (int mi = 0; mi < 4; mi++)
        #pragma unroll
        for (int ni = 0; ni < 2; ni++)
            #pragma unroll
            for (int r = 0; r < 4; r++) acc[mi][ni][r] = 0.f;

    #pragma unroll 1
    for (int kb = 0; kb < 4; kb++) {
        // ---- stage A: 128 o-rows x 8 uint4 (64 c), hi+lo ------------------
        #pragma unroll
        for (int f = tid; f < 1024; f += 256) {
            int o = f >> 3, q = f & 7;
            uint4 vh = ((const uint4*)Ah)[(o0 + o) * 32 + kb * 8 + q];
            uint4 vl = ((const uint4*)Al)[(o0 + o) * 32 + kb * 8 + q];
            ((uint4*)(su + AH_OFF + o * APITCH))[q] = vh;
            ((uint4*)(su + AL_OFF + o * APITCH))[q] = vl;
        }
        // ---- stage B: 64 p-rows x 8 uint4 (64 c), hi+lo -------------------
        #pragma unroll
        for (int f = tid; f < 512; f += 256) {
            int p = f >> 3, q = f & 7;
            uint4 vh = ((const uint4*)Xh)[(size_t)(p0 + p) * 32 + kb * 8 + q];
            uint4 vl = ((const uint4*)Xl)[(size_t)(p0 + p) * 32 + kb * 8 + q];
            ((uint4*)(su + BH_OFF + p * APITCH))[q] = vh;
            ((uint4*)(su + BL_OFF + p * APITCH))[q] = vl;
        }
        __syncthreads();

        // ---- compute: 4 k-steps of 16 -------------------------------------
        #pragma unroll 1
        for (int ks = 0; ks < 4; ks++) {
            const int k0w = ks * 8;
            uint32_t bh[2][2], bl[2][2];
            #pragma unroll
            for (int ni = 0; ni < 2; ni++) {
                int n = nw * 16 + ni * 8 + gq;
                int base = BH_OFF + n * APITCH + k0w + l4;
                bh[ni][0] = su[base];
                bh[ni][1] = su[base + 4];
                bl[ni][0] = su[base + (BL_OFF - BH_OFF)];
                bl[ni][1] = su[base + (BL_OFF - BH_OFF) + 4];
            }
            #pragma unroll
            for (int mi = 0; mi < 4; mi++) {
                int row = mw * 64 + mi * 16 + gq;
                int base = AH_OFF + row * APITCH + k0w + l4;
                uint32_t ah[4], al[4];
                ah[0] = su[base];
                ah[1] = su[base + 8 * APITCH];
                ah[2] = su[base + 4];
                ah[3] = su[base + 8 * APITCH + 4];
                al[0] = su[base + AL_OFF];
                al[1] = su[base + AL_OFF + 8 * APITCH];
                al[2] = su[base + AL_OFF + 4];
                al[3] = su[base + AL_OFF + 8 * APITCH + 4];
                #pragma unroll
                for (int ni = 0; ni < 2; ni++) {
                    mma16816(acc[mi][ni], ah, bh[ni]);
                    mma16816(acc[mi][ni], ah, bl[ni]);
                    mma16816(acc[mi][ni], al, bh[ni]);
                }
            }
        }
        __syncthreads();
    }

    // ---- epilogue --------------------------------------------------------
    if (MODE == 1) {
        #pragma unroll
        for (int mi = 0; mi < 4; mi++) {
            int o = o0 + mw * 64 + mi * 16 + gq;
            float b0 = bias[o], b1 = bias[o + 8];
            #pragma unroll
            for (int ni = 0; ni < 2; ni++) {
                int p = p0 + nw * 16 + ni * 8 + l4 * 2;
                float2 v0 = { acc[mi][ni][0] + b0, acc[mi][ni][1] + b0 };
                float2 v1 = { acc[mi][ni][2] + b1, acc[mi][ni][3] + b1 };
                *(float2*)(out + (size_t)o * HW + p)       = v0;
                *(float2*)(out + (size_t)(o + 8) * HW + p) = v1;
            }
        }
    } else {
        // row class (o mod 8) == gq for every acc this thread holds
        float* red = (float*)su;                 // 8 x 64
        for (int t = tid; t < 512; t += 256) red[t] = -INFINITY;
        __syncthreads();
        float bo[4][2];
        #pragma unroll
        for (int mi = 0; mi < 4; mi++) {
            int o = o0 + mw * 64 + mi * 16 + gq;
            bo[mi][0] = bias[o];
            bo[mi][1] = bias[o + 8];
        }
        #pragma unroll
        for (int ni = 0; ni < 2; ni++) {
            #pragma unroll
            for (int l = 0; l < 2; l++) {
                int col = nw * 16 + ni * 8 + l4 * 2 + l;
                float m = -INFINITY;
                #pragma unroll
                for (int mi = 0; mi < 4; mi++) {
                    m = fmaxf(m, acc[mi][ni][l]     + bo[mi][0]);
                    m = fmaxf(m, acc[mi][ni][2 + l] + bo[mi][1]);
                }
                atomicMaxFloat(&red[gq * 64 + col], m);
            }
        }
        __syncthreads();
        for (int t = tid; t < 512; t += 256) {
            int cls = t >> 6, col = t & 63;
            unsigned idx = ((unsigned)cls * 9216u + (unsigned)(p0 + col)) % 24576u;
            atomicMaxFloat(&g_FQM[idx], red[t]);
        }
    }
}

// ---------------------------------------------------------------------------
// out[e] *= (1 + g_FQM[e % 24576]), float4.
__global__ __launch_bounds__(256) void mask_epilogue(float* __restrict__ out) {
    unsigned v = blockIdx.x * 256u + threadIdx.x;
    unsigned idx = (v * 4u) % 24576u;
    float4 o = ((float4*)out)[v];
    float4 m = *(const float4*)&g_FQM[idx];
    o.x *= (1.0f + m.x);
    o.y *= (1.0f + m.y);
    o.z *= (1.0f + m.z);
    o.w *= (1.0f + m.w);
    ((float4*)out)[v] = o;
}

// ---------------------------------------------------------------------------
extern "C" void kernel_launch(void* const* d_in, const int* in_sizes, int n_in,
                              void* d_out, int out_size) {
    const float* fuse = (const float*)d_in[0];
    const float* Wq   = (const float*)d_in[1];
    const float* bq   = (const float*)d_in[2];
    // d_in[3] (Wk), d_in[4] (bk): dead code — softmax over batch axis of size 1
    const float* Wv   = (const float*)d_in[5];
    const float* bv   = (const float*)d_in[6];
    float* out = (float*)d_out;

    cudaFuncSetAttribute(gemm_mma<0>,
        cudaFuncAttributeMaxDynamicSharedMemorySize, SMEM_U32 * 4);
    cudaFuncSetAttribute(gemm_mma<1>,
        cudaFuncAttributeMaxDynamicSharedMemorySize, SMEM_U32 * 4);

    static cudaStream_t s1 = nullptr;
    static cudaEvent_t evRoot = nullptr, evW = nullptr, evG0 = nullptr;
    if (s1 == nullptr) {
        cudaStreamCreateWithFlags(&s1, cudaStreamNonBlocking);
        cudaEventCreateWithFlags(&evRoot, cudaEventDisableTiming);
        cudaEventCreateWithFlags(&evW, cudaEventDisableTiming);
        cudaEventCreateWithFlags(&evG0, cudaEventDisableTiming);
    }

    // Fork side stream for the full Q-mask chain.
    cudaEventRecord(evRoot, 0);
    cudaStreamWaitEvent(s1, evRoot, 0);

    // Main: W convert (needed by both GEMMs), X transpose, V-GEMM.
    convert_w<<<128, 256>>>(Wq, Wv);
    cudaEventRecord(evW, 0);
    transpose_convert<0><<<dim3(144, 8), 256>>>(fuse);             // fuse -> X^T
    gemm_mma<1><<<dim3(144, 2), 256, SMEM_U32 * 4>>>(bv, out);

    // Side: freq -> FQ^T -> Q-GEMM (produces g_FQM).
    freq_kernel<<<C_DIM, 512, 0, s1>>>(fuse);          // also inits g_FQM
    transpose_convert<1><<<dim3(144, 8), 256, 0, s1>>>(nullptr);   // FQ -> FQ^T
    cudaStreamWaitEvent(s1, evW, 0);
    gemm_mma<0><<<dim3(144, 2), 256, SMEM_U32 * 4, s1>>>(bq, nullptr);
    cudaEventRecord(evG0, s1);

    // Join: mask needs both out (gemm<1>, main) and g_FQM (gemm<0>, side).
    cudaStreamWaitEvent(0, evG0, 0);
    mask_epilogue<<<NPIX / 4 / 256, 256>>>(out);
}

// round 15
// speedup vs baseline: 1.1156x; 1.1156x over previous
#include <cuda_runtime.h>
#include <cuda_bf16.h>
#include <math.h>
#include <stdint.h>

// Problem constants: B=1, C=256, H=W=96
#define C_DIM 256
#define HDIM  96
#define HW    9216          // H*W
#define CW    24576         // C*W
#define NPIX  (C_DIM*HW)    // 2359296

// ---------------------------------------------------------------------------
// Device-global scratch. bf16 split hi/lo, packed bf16x2 (uint32).
__device__ float    g_FQ[NPIX];                     // fp32 FQ [ch][p]
__device__ uint32_t g_Xth[NPIX/2],  g_Xtl[NPIX/2];  // fuse^T hi/lo [p][c/2]
__device__ uint32_t g_FQth[NPIX/2], g_FQtl[NPIX/2]; // FQ^T   hi/lo [p][c/2]
__device__ uint32_t g_Wh0[32768], g_Wl0[32768];     // Wq hi/lo [o][c/2]
__device__ uint32_t g_Wh1[32768], g_Wl1[32768];     // Wv hi/lo [o][c/2]
__device__ float    g_FQM[CW];                      // Fuse_Q_mask

// ---------------------------------------------------------------------------
__device__ __forceinline__ void atomicMaxFloat(float* addr, float val) {
    if (val >= 0.0f) atomicMax((int*)addr, __float_as_int(val));
    else             atomicMin((unsigned int*)addr, __float_as_uint(val));
}

__device__ __forceinline__ uint32_t pack_bf2(float a, float b) {
    __nv_bfloat16 ha = __float2bfloat16_rn(a);
    __nv_bfloat16 hb = __float2bfloat16_rn(b);
    unsigned short ua = *reinterpret_cast<unsigned short*>(&ha);
    unsigned short ub = *reinterpret_cast<unsigned short*>(&hb);
    return (uint32_t)ua | ((uint32_t)ub << 16);
}
__device__ __forceinline__ float bf_hi_val(float a) {
    __nv_bfloat16 h = __float2bfloat16_rn(a);
    return __bfloat162float(h);
}

// m16n8k16 bf16 MMA, fp32 accumulate (standard PTX, compiles on plain sm_103)
__device__ __forceinline__ void mma16816(float* d, const uint32_t* a,
                                         const uint32_t* b) {
    asm volatile(
        "mma.sync.aligned.m16n8k16.row.col.f32.bf16.bf16.f32 "
        "{%0,%1,%2,%3}, {%4,%5,%6,%7}, {%8,%9}, {%0,%1,%2,%3};"
        : "+f"(d[0]), "+f"(d[1]), "+f"(d[2]), "+f"(d[3])
        : "r"(a[0]), "r"(a[1]), "r"(a[2]), "r"(a[3]), "r"(b[0]), "r"(b[1]));
}

// ---------------------------------------------------------------------------
// Convert Wq, Wv to split bf16 hi/lo (row-major [o][c/2], no transpose).
__global__ __launch_bounds__(256) void convert_w(
    const float* __restrict__ Wq, const float* __restrict__ Wv)
{
    unsigned v = blockIdx.x * 256u + threadIdx.x;   // float4 index
    const float* src; uint32_t *dh, *dl; unsigned base;
    if (v < 16384)      { src = Wq; dh = g_Wh0; dl = g_Wl0; base = v; }
    else if (v < 32768) { src = Wv; dh = g_Wh1; dl = g_Wl1; base = v - 16384; }
    else return;
    float4 x = ((const float4*)src)[base];
    float h0 = bf_hi_val(x.x), h1 = bf_hi_val(x.y);
    float h2 = bf_hi_val(x.z), h3 = bf_hi_val(x.w);
    dh[2*base]   = pack_bf2(x.x, x.y);
    dh[2*base+1] = pack_bf2(x.z, x.w);
    dl[2*base]   = pack_bf2(x.x - h0, x.y - h1);
    dl[2*base+1] = pack_bf2(x.z - h2, x.w - h3);
}

// ---------------------------------------------------------------------------
// Transpose + split-convert: src fp32 [256][9216] -> dh/dl u32 [9216][128].
// SRC=0: src = xin (fuse), dest = g_Xth/g_Xtl.
// SRC=1: src = g_FQ (bound IN DEVICE CODE), dest = g_FQth/tl.
template <int SRC>
__global__ __launch_bounds__(256) void transpose_convert(
    const float* __restrict__ xin)
{
    const float* src = (SRC == 0) ? xin : (const float*)g_FQ;
    uint32_t* dh = (SRC == 0) ? g_Xth : g_FQth;
    uint32_t* dl = (SRC == 0) ? g_Xtl : g_FQtl;

    __shared__ float ts[32][65];
    const int p0 = blockIdx.x * 64;
    const int c0 = blockIdx.y * 32;
    const int tid = threadIdx.x;
    #pragma unroll
    for (int k = 0; k < 8; k++) {
        int idx = k * 256 + tid;
        int c = idx >> 6, p = idx & 63;
        ts[c][p] = src[(size_t)(c0 + c) * HW + p0 + p];
    }
    __syncthreads();
    #pragma unroll
    for (int k = 0; k < 4; k++) {
        int idx = k * 256 + tid;
        int p = idx >> 4, cw = idx & 15;
        float a = ts[2*cw][p], b = ts[2*cw + 1][p];
        float ah = bf_hi_val(a), bh = bf_hi_val(b);
        size_t o = (size_t)(p0 + p) * 128 + (c0 >> 1) + cw;
        dh[o] = pack_bf2(a, b);
        dl[o] = pack_bf2(a - ah, b - bh);
    }
}

// ---------------------------------------------------------------------------
// Per-channel frequency filter v3: conflict-free smem (pitch 97), conjugate
// symmetry (G[-k]=conj(G[k])) -> stage 1 is 5 conflict-free LDS + 5 FLOP/iter.
// Keep DFT freqs kr,kc in {-2..1}, inverse-synthesize, abs, /9216 -> g_FQ.
__global__ __launch_bounds__(512) void freq_kernel(const float* __restrict__ x) {
    __shared__ float sa[96 * 97];             // pitch 97 (97%32=1): no conflicts
    __shared__ float sc1[96], ss1[96], sc2[96], ss2[96];
    __shared__ unsigned char pidx[4][96];     // ((k-2)*v) mod 96 (stage2/sP)
    __shared__ float Gp[4][4][96][2];         // (h-quarter, krIdx, w, re/im)
    __shared__ float s2p[64][2];
    __shared__ float sF[32];
    __shared__ float sP[4][96][2];
    __shared__ float sMin[16], sMax[16];

    const int ch  = blockIdx.x;
    const int tid = threadIdx.x;

    if (ch < 48) g_FQM[ch * 512 + tid] = -INFINITY;   // init Fuse_Q_mask buffer

    if (tid < 96) {  // twiddles, fp64 trig: c1=cos(th), c2=cos(2*th mod 2pi)
        double th = 2.0 * 3.14159265358979323846 * (double)tid / 96.0;
        int m2 = (2 * tid) % 96;
        double th2 = 2.0 * 3.14159265358979323846 * (double)m2 / 96.0;
        sc1[tid] = (float)cos(th);
        ss1[tid] = (float)sin(th);
        sc2[tid] = (float)cos(th2);
        ss2[tid] = (float)sin(th2);
    }
    if (tid >= 128 && tid < 512) {            // phase index table (384 entries)
        int t = tid - 128;
        int k = t / 96, v = t - k * 96;
        int m = ((k - 2) * v) % 96; if (m < 0) m += 96;
        pidx[k][v] = (unsigned char)m;
    }

    // ---- vectorized |x| load -> sa (pitch 97), block min/max --------------
    const float4* xc4 = (const float4*)(x + (size_t)ch * HW);
    float lmin = INFINITY, lmax = -INFINITY;
    #pragma unroll
    for (int k = 0; k < 5; k++) {
        int i4 = k * 512 + tid;
        if (i4 < 2304) {
            float4 v = xc4[i4];
            float a0 = fabsf(v.x), a1 = fabsf(v.y);
            float a2 = fabsf(v.z), a3 = fabsf(v.w);
            int h = i4 / 24;                  // 24 float4 per image row
            int w = (i4 - h * 24) * 4;
            float* dst = sa + h * 97 + w;
            dst[0] = a0; dst[1] = a1; dst[2] = a2; dst[3] = a3;
            lmin = fminf(lmin, fminf(fminf(a0, a1), fminf(a2, a3)));
            lmax = fmaxf(lmax, fmaxf(fmaxf(a0, a1), fmaxf(a2, a3)));
        }
    }
    #pragma unroll
    for (int off = 16; off; off >>= 1) {
        lmin = fminf(lmin, __shfl_down_sync(0xffffffffu, lmin, off));
        lmax = fmaxf(lmax, __shfl_down_sync(0xffffffffu, lmax, off));
    }
    const int wid = tid >> 5, lane = tid & 31;
    if (lane == 0) { sMin[wid] = lmin; sMax[wid] = lmax; }
    __syncthreads();

    float mn = sMin[0], mx = sMax[0];
    #pragma unroll
    for (int j = 1; j < 16; j++) { mn = fminf(mn, sMin[j]); mx = fmaxf(mx, sMax[j]); }
    const float s255 = 255.0f / (mx - mn);

    // ---- stage 1: column DFT over h via G0/G1/G2 + conjugate expand -------
    if (tid < 384) {
        const int w  = tid >> 2;
        const int qh = tid & 3;
        const int h0 = qh * 24;
        float G0 = 0.f, G1r = 0.f, G1p = 0.f, G2r = 0.f, G2p = 0.f;
        #pragma unroll 4
        for (int j = 0; j < 24; j++) {
            int h = h0 + j;
            float q = floorf((sa[h * 97 + w] - mn) * s255);
            float c1v = sc1[h], s1v = ss1[h];
            float c2v = sc2[h], s2v = ss2[h];
            G0  += q;
            G1r += q * c1v; G1p += q * s1v;
            G2r += q * c2v; G2p += q * s2v;
        }
        // krIdx: 0 = kr-2, ..., 3 = kr+1;  G[kr] = sum q e^{-i kr th}
        Gp[qh][0][w][0] = G2r; Gp[qh][0][w][1] =  G2p;   // kr=-2: conj(G2)
        Gp[qh][1][w][0] = G1r; Gp[qh][1][w][1] =  G1p;   // kr=-1: conj(G1)
        Gp[qh][2][w][0] = G0;  Gp[qh][2][w][1] =  0.f;   // kr= 0
        Gp[qh][3][w][0] = G1r; Gp[qh][3][w][1] = -G1p;   // kr=+1
    }
    __syncthreads();

    // ---- stage 2: 16 coefficients, 64-way parallel then 4:1 combine -------
    if (tid < 64) {
        int coef = tid >> 2, q4 = tid & 3;
        int kr = coef >> 2, kc = coef & 3;
        float fr = 0.f, fi = 0.f;
        int w0 = q4 * 24;
        for (int w = w0; w < w0 + 24; w++) {
            float grw = Gp[0][kr][w][0] + Gp[1][kr][w][0]
                      + Gp[2][kr][w][0] + Gp[3][kr][w][0];
            float giw = Gp[0][kr][w][1] + Gp[1][kr][w][1]
                      + Gp[2][kr][w][1] + Gp[3][kr][w][1];
            int m = pidx[kc][w];
            float cc = sc1[m], ss = ss1[m];
            fr += grw * cc + giw * ss;
            fi += giw * cc - grw * ss;
        }
        s2p[tid][0] = fr;
        s2p[tid][1] = fi;
    }
    __syncthreads();
    if (tid < 32) {
        int coef = tid >> 1, ri = tid & 1;
        sF[coef * 2 + ri] = s2p[coef * 4][ri] + s2p[coef * 4 + 1][ri]
                          + s2p[coef * 4 + 2][ri] + s2p[coef * 4 + 3][ri];
    }
    __syncthreads();

    // ---- synthesis: column partials over kc -------------------------------
    if (tid < 96) {
        int w = tid;
        #pragma unroll
        for (int kr = 0; kr < 4; kr++) {
            float pre = 0.f, pim = 0.f;
            #pragma unroll
            for (int kc = 0; kc < 4; kc++) {
                int m = pidx[kc][w];
                float fr = sF[2 * (kr * 4 + kc)], fi = sF[2 * (kr * 4 + kc) + 1];
                float cc = sc1[m], ss = ss1[m];
                pre += fr * cc - fi * ss;
                pim += fr * ss + fi * cc;
            }
            sP[kr][w][0] = pre;
            sP[kr][w][1] = pim;
        }
    }
    __syncthreads();

    // ---- per-pixel inverse + abs, 4 pixels / thread, float4 stores --------
    // e^{+i kr th(h)}: kr=-2 -> (c2,-s2), kr=-1 -> (c1,-s1), 0 -> (1,0), 1 -> (c1,s1)
    const float inv = 1.0f / 9216.0f;
    float4* fq4 = (float4*)(g_FQ + (size_t)ch * HW);
    #pragma unroll
    for (int k = 0; k < 5; k++) {
        int i4 = k * 512 + tid;
        if (i4 < 2304) {
            int pix = i4 * 4;
            int h = pix / 96, w0 = pix - h * 96;   // 4 pixels share one row
            float c1v = sc1[h], s1v = ss1[h];
            float c2v = sc2[h], s2v = ss2[h];
            float cr[4] = { c2v,  c1v, 1.f, c1v };
            float sr[4] = { -s2v, -s1v, 0.f, s1v };
            float vv[4];
            #pragma unroll
            for (int dw = 0; dw < 4; dw++) {
                float re = 0.f, im = 0.f;
                #pragma unroll
                for (int kr = 0; kr < 4; kr++) {
                    float pre = sP[kr][w0 + dw][0], pim = sP[kr][w0 + dw][1];
                    re += pre * cr[kr] - pim * sr[kr];
                    im += pre * sr[kr] + pim * cr[kr];
                }
                vv[dw] = sqrtf(re * re + im * im) * inv;
            }
            fq4[i4] = make_float4(vv[0], vv[1], vv[2], vv[3]);
        }
    }
}

// ---------------------------------------------------------------------------
// Split-precision bf16 GEMM via mma.sync.m16n8k16 (HMMA tensor pipe).
// out[o,p] = sum_c W[o,c] X[c,p] + bias[o],  O=256, P=9216, K=256.
// CTA tile: M=128 x N=64, K staged in 4 phases of 64. 55 KB smem -> 2 CTA/SM.
// MODE 0 (Q): X = FQ^T, epilogue class-max into g_FQM.
// MODE 1 (V): X = fuse^T, writes raw (acc+bias) to out.
#define APITCH 36            // u32 per smem row (36%32=4 -> no conflicts)
#define AH_OFF 0
#define AL_OFF 4608          // 128*36
#define BH_OFF 9216
#define BL_OFF 11520         // +64*36
#define SMEM_U32 13824       // 55296 bytes

template <int MODE>
__global__ __launch_bounds__(256, 2) void gemm_mma(
    const float* __restrict__ bias, float* __restrict__ out)
{
    extern __shared__ uint32_t su[];
    const int tid  = threadIdx.x;
    const int wid  = tid >> 5, lane = tid & 31;
    const int mw   = wid >> 2, nw = wid & 3;     // 2m x 4n warp grid
    const int gq   = lane >> 2, l4 = lane & 3;   // groupID, threadID-in-group
    const int p0   = blockIdx.x * 64;
    const int o0   = blockIdx.y * 128;

    const uint32_t* Ah = (MODE == 0) ? g_Wh0  : g_Wh1;
    const uint32_t* Al = (MODE == 0) ? g_Wl0  : g_Wl1;
    const uint32_t* Xh = (MODE == 0) ? g_FQth : g_Xth;
    const uint32_t* Xl = (MODE == 0) ? g_FQtl : g_Xtl;

    float acc[4][2][4];
    #pragma unroll
    for (int mi = 0; mi < 4; mi++)
        #pragma unroll
        for (int ni = 0; ni < 2; ni++)
            #pragma unroll
            for (int r = 0; r < 4; r++) acc[mi][ni][r] = 0.f;

    #pragma unroll 1
    for (int kb = 0; kb < 4; kb++) {
        #pragma unroll
        for (int f = tid; f < 1024; f += 256) {
            int o = f >> 3, q = f & 7;
            uint4 vh = ((const uint4*)Ah)[(o0 + o) * 32 + kb * 8 + q];
            uint4 vl = ((const uint4*)Al)[(o0 + o) * 32 + kb * 8 + q];
            ((uint4*)(su + AH_OFF + o * APITCH))[q] = vh;
            ((uint4*)(su + AL_OFF + o * APITCH))[q] = vl;
        }
        #pragma unroll
        for (int f = tid; f < 512; f += 256) {
            int p = f >> 3, q = f & 7;
            uint4 vh = ((const uint4*)Xh)[(size_t)(p0 + p) * 32 + kb * 8 + q];
            uint4 vl = ((const uint4*)Xl)[(size_t)(p0 + p) * 32 + kb * 8 + q];
            ((uint4*)(su + BH_OFF + p * APITCH))[q] = vh;
            ((uint4*)(su + BL_OFF + p * APITCH))[q] = vl;
        }
        __syncthreads();

        #pragma unroll 1
        for (int ks = 0; ks < 4; ks++) {
            const int k0w = ks * 8;
            uint32_t bh[2][2], bl[2][2];
            #pragma unroll
            for (int ni = 0; ni < 2; ni++) {
                int n = nw * 16 + ni * 8 + gq;
                int base = BH_OFF + n * APITCH + k0w + l4;
                bh[ni][0] = su[base];
                bh[ni][1] = su[base + 4];
                bl[ni][0] = su[base + (BL_OFF - BH_OFF)];
                bl[ni][1] = su[base + (BL_OFF - BH_OFF) + 4];
            }
            #pragma unroll
            for (int mi = 0; mi < 4; mi++) {
                int row = mw * 64 + mi * 16 + gq;
                int base = AH_OFF + row * APITCH + k0w + l4;
                uint32_t ah[4], al[4];
                ah[0] = su[base];
                ah[1] = su[base + 8 * APITCH];
                ah[2] = su[base + 4];
                ah[3] = su[base + 8 * APITCH + 4];
                al[0] = su[base + AL_OFF];
                al[1] = su[base + AL_OFF + 8 * APITCH];
                al[2] = su[base + AL_OFF + 4];
                al[3] = su[base + AL_OFF + 8 * APITCH + 4];
                #pragma unroll
                for (int ni = 0; ni < 2; ni++) {
                    mma16816(acc[mi][ni], ah, bh[ni]);
                    mma16816(acc[mi][ni], ah, bl[ni]);
                    mma16816(acc[mi][ni], al, bh[ni]);
                }
            }
        }
        __syncthreads();
    }

    if (MODE == 1) {
        #pragma unroll
        for (int mi = 0; mi < 4; mi++) {
            int o = o0 + mw * 64 + mi * 16 + gq;
            float b0 = bias[o], b1 = bias[o + 8];
            #pragma unroll
            for (int ni = 0; ni < 2; ni++) {
                int p = p0 + nw * 16 + ni * 8 + l4 * 2;
                float2 v0 = { acc[mi][ni][0] + b0, acc[mi][ni][1] + b0 };
                float2 v1 = { acc[mi][ni][2] + b1, acc[mi][ni][3] + b1 };
                *(float2*)(out + (size_t)o * HW + p)       = v0;
                *(float2*)(out + (size_t)(o + 8) * HW + p) = v1;
            }
        }
    } else {
        float* red = (float*)su;                 // 8 x 64
        for (int t = tid; t < 512; t += 256) red[t] = -INFINITY;
        __syncthreads();
        float bo[4][2];
        #pragma unroll
        for (int mi = 0; mi < 4; mi++) {
            int o = o0 + mw * 64 + mi * 16 + gq;
            bo[mi][0] = bias[o];
            bo[mi][1] = bias[o + 8];
        }
        #pragma unroll
        for (int ni = 0; ni < 2; ni++) {
            #pragma unroll
            for (int l = 0; l < 2; l++) {
                int col = nw * 16 + ni * 8 + l4 * 2 + l;
                float m = -INFINITY;
                #pragma unroll
                for (int mi = 0; mi < 4; mi++) {
                    m = fmaxf(m, acc[mi][ni][l]     + bo[mi][0]);
                    m = fmaxf(m, acc[mi][ni][2 + l] + bo[mi][1]);
                }
                atomicMaxFloat(&red[gq * 64 + col], m);
            }
        }
        __syncthreads();
        for (int t = tid; t < 512; t += 256) {
            int cls = t >> 6, col = t & 63;
            unsigned idx = ((unsigned)cls * 9216u + (unsigned)(p0 + col)) % 24576u;
            atomicMaxFloat(&g_FQM[idx], red[t]);
        }
    }
}

// ---------------------------------------------------------------------------
// out[e] *= (1 + g_FQM[e % 24576]), float4.
__global__ __launch_bounds__(256) void mask_epilogue(float* __restrict__ out) {
    unsigned v = blockIdx.x * 256u + threadIdx.x;
    unsigned idx = (v * 4u) % 24576u;
    float4 o = ((float4*)out)[v];
    float4 m = *(const float4*)&g_FQM[idx];
    o.x *= (1.0f + m.x);
    o.y *= (1.0f + m.y);
    o.z *= (1.0f + m.z);
    o.w *= (1.0f + m.w);
    ((float4*)out)[v] = o;
}

// ---------------------------------------------------------------------------
extern "C" void kernel_launch(void* const* d_in, const int* in_sizes, int n_in,
                              void* d_out, int out_size) {
    const float* fuse = (const float*)d_in[0];
    const float* Wq   = (const float*)d_in[1];
    const float* bq   = (const float*)d_in[2];
    // d_in[3] (Wk), d_in[4] (bk): dead code — softmax over batch axis of size 1
    const float* Wv   = (const float*)d_in[5];
    const float* bv   = (const float*)d_in[6];
    float* out = (float*)d_out;

    cudaFuncSetAttribute(gemm_mma<0>,
        cudaFuncAttributeMaxDynamicSharedMemorySize, SMEM_U32 * 4);
    cudaFuncSetAttribute(gemm_mma<1>,
        cudaFuncAttributeMaxDynamicSharedMemorySize, SMEM_U32 * 4);

    static cudaStream_t s1 = nullptr;
    static cudaEvent_t evRoot = nullptr, evT = nullptr;
    if (s1 == nullptr) {
        cudaStreamCreateWithFlags(&s1, cudaStreamNonBlocking);
        cudaEventCreateWithFlags(&evRoot, cudaEventDisableTiming);
        cudaEventCreateWithFlags(&evT, cudaEventDisableTiming);
    }

    // R13 schedule (best measured): side = freq chain; main = V path; join;
    // then Q-GEMM + mask on main.
    cudaEventRecord(evRoot, 0);
    cudaStreamWaitEvent(s1, evRoot, 0);
    freq_kernel<<<C_DIM, 512, 0, s1>>>(fuse);          // also inits g_FQM
    transpose_convert<1><<<dim3(144, 8), 256, 0, s1>>>(nullptr);   // FQ -> FQ^T
    cudaEventRecord(evT, s1);

    convert_w<<<128, 256>>>(Wq, Wv);
    transpose_convert<0><<<dim3(144, 8), 256>>>(fuse);             // fuse -> X^T
    gemm_mma<1><<<dim3(144, 2), 256, SMEM_U32 * 4>>>(bv, out);
    cudaStreamWaitEvent(0, evT, 0);
    gemm_mma<0><<<dim3(144, 2), 256, SMEM_U32 * 4>>>(bq, nullptr);
    mask_epilogue<<<NPIX / 4 / 256, 256>>>(out);
}

// round 16
// speedup vs baseline: 1.1186x; 1.0027x over previous
#include <cuda_runtime.h>
#include <cuda_bf16.h>
#include <math.h>
#include <stdint.h>

// Problem constants: B=1, C=256, H=W=96
#define C_DIM 256
#define HDIM  96
#define HW    9216          // H*W
#define CW    24576         // C*W
#define NPIX  (C_DIM*HW)    // 2359296

// ---------------------------------------------------------------------------
// Device-global scratch. bf16 split hi/lo, packed bf16x2 (uint32).
// X / FQ layouts: [c][p/2] (pairs along p). W: [o][c/2] (pairs along c).
__device__ uint32_t g_Xh[NPIX/2],  g_Xl[NPIX/2];    // fuse hi/lo [c][p/2]
__device__ uint32_t g_FQh[NPIX/2], g_FQl[NPIX/2];   // FQ   hi/lo [c][p/2]
__device__ uint32_t g_Wh0[32768], g_Wl0[32768];     // Wq hi/lo [o][c/2]
__device__ uint32_t g_Wh1[32768], g_Wl1[32768];     // Wv hi/lo [o][c/2]
__device__ float    g_FQM[CW];                      // Fuse_Q_mask

// ---------------------------------------------------------------------------
__device__ __forceinline__ void atomicMaxFloat(float* addr, float val) {
    if (val >= 0.0f) atomicMax((int*)addr, __float_as_int(val));
    else             atomicMin((unsigned int*)addr, __float_as_uint(val));
}

__device__ __forceinline__ uint32_t pack_bf2(float a, float b) {
    __nv_bfloat16 ha = __float2bfloat16_rn(a);
    __nv_bfloat16 hb = __float2bfloat16_rn(b);
    unsigned short ua = *reinterpret_cast<unsigned short*>(&ha);
    unsigned short ub = *reinterpret_cast<unsigned short*>(&hb);
    return (uint32_t)ua | ((uint32_t)ub << 16);
}
__device__ __forceinline__ float bf_hi_val(float a) {
    __nv_bfloat16 h = __float2bfloat16_rn(a);
    return __bfloat162float(h);
}

// m16n8k16 bf16 MMA, fp32 accumulate (standard PTX, compiles on plain sm_103)
__device__ __forceinline__ void mma16816(float* d, const uint32_t* a,
                                         const uint32_t* b) {
    asm volatile(
        "mma.sync.aligned.m16n8k16.row.col.f32.bf16.bf16.f32 "
        "{%0,%1,%2,%3}, {%4,%5,%6,%7}, {%8,%9}, {%0,%1,%2,%3};"
        : "+f"(d[0]), "+f"(d[1]), "+f"(d[2]), "+f"(d[3])
        : "r"(a[0]), "r"(a[1]), "r"(a[2]), "r"(a[3]), "r"(b[0]), "r"(b[1]));
}

// ---------------------------------------------------------------------------
// Convert fuse, Wq, Wv to split bf16 hi/lo pairs (elementwise, coalesced).
__global__ __launch_bounds__(256) void convert_kernel(
    const float* __restrict__ fuse, const float* __restrict__ Wq,
    const float* __restrict__ Wv)
{
    unsigned v = blockIdx.x * 256u + threadIdx.x;   // float4 index
    const float* src; uint32_t *dh, *dl; unsigned base;
    if (v < NPIX/4)              { src = fuse; dh = g_Xh;  dl = g_Xl;  base = v; }
    else if (v < NPIX/4 + 16384) { src = Wq;   dh = g_Wh0; dl = g_Wl0; base = v - NPIX/4; }
    else if (v < NPIX/4 + 32768) { src = Wv;   dh = g_Wh1; dl = g_Wl1; base = v - NPIX/4 - 16384; }
    else return;
    float4 x = ((const float4*)src)[base];
    float h0 = bf_hi_val(x.x), h1 = bf_hi_val(x.y);
    float h2 = bf_hi_val(x.z), h3 = bf_hi_val(x.w);
    dh[2*base]   = pack_bf2(x.x, x.y);
    dh[2*base+1] = pack_bf2(x.z, x.w);
    dl[2*base]   = pack_bf2(x.x - h0, x.y - h1);
    dl[2*base+1] = pack_bf2(x.z - h2, x.w - h3);
}

// ---------------------------------------------------------------------------
// Per-channel frequency filter v3 (proven R15): conflict-free smem (pitch 97),
// conjugate symmetry. Emits FQ directly as packed bf16 hi/lo [c][p/2].
__global__ __launch_bounds__(512) void freq_kernel(const float* __restrict__ x) {
    __shared__ float sa[96 * 97];             // pitch 97 (97%32=1): no conflicts
    __shared__ float sc1[96], ss1[96], sc2[96], ss2[96];
    __shared__ unsigned char pidx[4][96];     // ((k-2)*v) mod 96 (stage2/sP)
    __shared__ float Gp[4][4][96][2];         // (h-quarter, krIdx, w, re/im)
    __shared__ float s2p[64][2];
    __shared__ float sF[32];
    __shared__ float sP[4][96][2];
    __shared__ float sMin[16], sMax[16];

    const int ch  = blockIdx.x;
    const int tid = threadIdx.x;

    if (ch < 48) g_FQM[ch * 512 + tid] = -INFINITY;   // init Fuse_Q_mask buffer

    if (tid < 96) {  // twiddles, fp64 trig
        double th = 2.0 * 3.14159265358979323846 * (double)tid / 96.0;
        int m2 = (2 * tid) % 96;
        double th2 = 2.0 * 3.14159265358979323846 * (double)m2 / 96.0;
        sc1[tid] = (float)cos(th);
        ss1[tid] = (float)sin(th);
        sc2[tid] = (float)cos(th2);
        ss2[tid] = (float)sin(th2);
    }
    if (tid >= 128 && tid < 512) {            // phase index table (384 entries)
        int t = tid - 128;
        int k = t / 96, v = t - k * 96;
        int m = ((k - 2) * v) % 96; if (m < 0) m += 96;
        pidx[k][v] = (unsigned char)m;
    }

    // ---- vectorized |x| load -> sa (pitch 97), block min/max --------------
    const float4* xc4 = (const float4*)(x + (size_t)ch * HW);
    float lmin = INFINITY, lmax = -INFINITY;
    #pragma unroll
    for (int k = 0; k < 5; k++) {
        int i4 = k * 512 + tid;
        if (i4 < 2304) {
            float4 v = xc4[i4];
            float a0 = fabsf(v.x), a1 = fabsf(v.y);
            float a2 = fabsf(v.z), a3 = fabsf(v.w);
            int h = i4 / 24;                  // 24 float4 per image row
            int w = (i4 - h * 24) * 4;
            float* dst = sa + h * 97 + w;
            dst[0] = a0; dst[1] = a1; dst[2] = a2; dst[3] = a3;
            lmin = fminf(lmin, fminf(fminf(a0, a1), fminf(a2, a3)));
            lmax = fmaxf(lmax, fmaxf(fmaxf(a0, a1), fmaxf(a2, a3)));
        }
    }
    #pragma unroll
    for (int off = 16; off; off >>= 1) {
        lmin = fminf(lmin, __shfl_down_sync(0xffffffffu, lmin, off));
        lmax = fmaxf(lmax, __shfl_down_sync(0xffffffffu, lmax, off));
    }
    const int wid = tid >> 5, lane = tid & 31;
    if (lane == 0) { sMin[wid] = lmin; sMax[wid] = lmax; }
    __syncthreads();

    float mn = sMin[0], mx = sMax[0];
    #pragma unroll
    for (int j = 1; j < 16; j++) { mn = fminf(mn, sMin[j]); mx = fmaxf(mx, sMax[j]); }
    const float s255 = 255.0f / (mx - mn);

    // ---- stage 1: column DFT over h via G0/G1/G2 + conjugate expand -------
    if (tid < 384) {
        const int w  = tid >> 2;
        const int qh = tid & 3;
        const int h0 = qh * 24;
        float G0 = 0.f, G1r = 0.f, G1p = 0.f, G2r = 0.f, G2p = 0.f;
        #pragma unroll 4
        for (int j = 0; j < 24; j++) {
            int h = h0 + j;
            float q = floorf((sa[h * 97 + w] - mn) * s255);
            G0  += q;
            G1r += q * sc1[h]; G1p += q * ss1[h];
            G2r += q * sc2[h]; G2p += q * ss2[h];
        }
        Gp[qh][0][w][0] = G2r; Gp[qh][0][w][1] =  G2p;   // kr=-2: conj(G2)
        Gp[qh][1][w][0] = G1r; Gp[qh][1][w][1] =  G1p;   // kr=-1: conj(G1)
        Gp[qh][2][w][0] = G0;  Gp[qh][2][w][1] =  0.f;   // kr= 0
        Gp[qh][3][w][0] = G1r; Gp[qh][3][w][1] = -G1p;   // kr=+1
    }
    __syncthreads();

    // ---- stage 2: 16 coefficients ----------------------------------------
    if (tid < 64) {
        int coef = tid >> 2, q4 = tid & 3;
        int kr = coef >> 2, kc = coef & 3;
        float fr = 0.f, fi = 0.f;
        int w0 = q4 * 24;
        for (int w = w0; w < w0 + 24; w++) {
            float grw = Gp[0][kr][w][0] + Gp[1][kr][w][0]
                      + Gp[2][kr][w][0] + Gp[3][kr][w][0];
            float giw = Gp[0][kr][w][1] + Gp[1][kr][w][1]
                      + Gp[2][kr][w][1] + Gp[3][kr][w][1];
            int m = pidx[kc][w];
            float cc = sc1[m], ss = ss1[m];
            fr += grw * cc + giw * ss;
            fi += giw * cc - grw * ss;
        }
        s2p[tid][0] = fr;
        s2p[tid][1] = fi;
    }
    __syncthreads();
    if (tid < 32) {
        int coef = tid >> 1, ri = tid & 1;
        sF[coef * 2 + ri] = s2p[coef * 4][ri] + s2p[coef * 4 + 1][ri]
                          + s2p[coef * 4 + 2][ri] + s2p[coef * 4 + 3][ri];
    }
    __syncthreads();

    // ---- synthesis: column partials over kc -------------------------------
    if (tid < 96) {
        int w = tid;
        #pragma unroll
        for (int kr = 0; kr < 4; kr++) {
            float pre = 0.f, pim = 0.f;
            #pragma unroll
            for (int kc = 0; kc < 4; kc++) {
                int m = pidx[kc][w];
                float fr = sF[2 * (kr * 4 + kc)], fi = sF[2 * (kr * 4 + kc) + 1];
                float cc = sc1[m], ss = ss1[m];
                pre += fr * cc - fi * ss;
                pim += fr * ss + fi * cc;
            }
            sP[kr][w][0] = pre;
            sP[kr][w][1] = pim;
        }
    }
    __syncthreads();

    // ---- per-pixel inverse + abs, 4 pixels/thread -> packed bf16 hi/lo ----
    const float inv = 1.0f / 9216.0f;
    uint2* fqh2 = (uint2*)g_FQh;   // channel stride 2304 uint2
    uint2* fql2 = (uint2*)g_FQl;
    #pragma unroll
    for (int k = 0; k < 5; k++) {
        int i4 = k * 512 + tid;
        if (i4 < 2304) {
            int pix = i4 * 4;
            int h = pix / 96, w0 = pix - h * 96;
            float c1v = sc1[h], s1v = ss1[h];
            float c2v = sc2[h], s2v = ss2[h];
            float cr[4] = { c2v,  c1v, 1.f, c1v };
            float sr[4] = { -s2v, -s1v, 0.f, s1v };
            float vv[4];
            #pragma unroll
            for (int dw = 0; dw < 4; dw++) {
                float re = 0.f, im = 0.f;
                #pragma unroll
                for (int kr = 0; kr < 4; kr++) {
                    float pre = sP[kr][w0 + dw][0], pim = sP[kr][w0 + dw][1];
                    re += pre * cr[kr] - pim * sr[kr];
                    im += pre * sr[kr] + pim * cr[kr];
                }
                vv[dw] = sqrtf(re * re + im * im) * inv;
            }
            uint32_t ph0 = pack_bf2(vv[0], vv[1]);
            uint32_t ph1 = pack_bf2(vv[2], vv[3]);
            uint32_t pl0 = pack_bf2(vv[0] - bf_hi_val(vv[0]), vv[1] - bf_hi_val(vv[1]));
            uint32_t pl1 = pack_bf2(vv[2] - bf_hi_val(vv[2]), vv[3] - bf_hi_val(vv[3]));
            fqh2[(size_t)ch * 2304 + i4] = make_uint2(ph0, ph1);
            fql2[(size_t)ch * 2304 + i4] = make_uint2(pl0, pl1);
        }
    }
}

// ---------------------------------------------------------------------------
// Split-precision bf16 GEMM via mma.sync.m16n8k16 (HMMA tensor pipe).
// out[o,p] = sum_c W[o,c] X[c,p] + bias[o],  O=256, P=9216, K=256.
// CTA tile: M=128 x N=64, K staged in 4 phases of 64. 55 KB smem -> 2 CTA/SM.
// B kept ROW-MAJOR [c][p] in smem; fragments loaded with ldmatrix.x4.trans
// (no pre-transposed global layout needed). A fragments via manual LDS.
// 3 passes: Ah*Bh + Ah*Bl + Al*Bh.
// MODE 0 (Q): X = FQ, epilogue class-max into g_FQM.
// MODE 1 (V): X = fuse, writes raw (acc+bias) to out.
#define APITCH 36            // u32 per A row  (36%32=4 -> conflict-free LDS)
#define BPITCH 36            // u32 per B row  (144B; 16B-group = k mod 8: ldmatrix-clean)
#define AH_OFF 0
#define AL_OFF 4608          // 128*36
#define BH_OFF 9216
#define BL_OFF 11520         // +64*36
#define SMEM_U32 13824       // 55296 bytes

template <int MODE>
__global__ __launch_bounds__(256, 2) void gemm_mma(
    const float* __restrict__ bias, float* __restrict__ out)
{
    extern __shared__ uint32_t su[];
    const int tid  = threadIdx.x;
    const int wid  = tid >> 5, lane = tid & 31;
    const int mw   = wid >> 2, nw = wid & 3;     // 2m x 4n warp grid
    const int gq   = lane >> 2, l4 = lane & 3;   // groupID, threadID-in-group
    const int p0   = blockIdx.x * 64;
    const int o0   = blockIdx.y * 128;

    const uint32_t* Ah = (MODE == 0) ? g_Wh0 : g_Wh1;
    const uint32_t* Al = (MODE == 0) ? g_Wl0 : g_Wl1;
    const uint32_t* Xh = (MODE == 0) ? g_FQh : g_Xh;
    const uint32_t* Xl = (MODE == 0) ? g_FQl : g_Xl;

    // ldmatrix lane address offset (bytes within B tile), constant per lane:
    // tile = lane/8: (tile&1) -> k-high 8, (tile>>1) -> n+8. row = lane%8.
    const int ltile = lane >> 3, lrow = lane & 7;
    const int lbyte = (((ltile & 1) << 3) + lrow) * 144
                    + ((nw << 4) + ((ltile >> 1) << 3)) * 2;
    const uint32_t sbase = (uint32_t)__cvta_generic_to_shared(su);
    const uint32_t baddr_h = sbase + BH_OFF * 4 + lbyte;
    const uint32_t baddr_l = sbase + BL_OFF * 4 + lbyte;

    float acc[4][2][4];
    #pragma unroll
    for (int mi = 0; mi < 4; mi++)
        #pragma unroll
        for (int ni = 0; ni < 2; ni++)
            #pragma unroll
            for (int r = 0; r < 4; r++) acc[mi][ni][r] = 0.f;

    #pragma unroll 1
    for (int kb = 0; kb < 4; kb++) {
        // ---- stage A: 128 o-rows x 8 uint4 (64 c), hi+lo ------------------
        #pragma unroll
        for (int f = tid; f < 1024; f += 256) {
            int o = f >> 3, q = f & 7;
            uint4 vh = ((const uint4*)Ah)[(o0 + o) * 32 + kb * 8 + q];
            uint4 vl = ((const uint4*)Al)[(o0 + o) * 32 + kb * 8 + q];
            ((uint4*)(su + AH_OFF + o * APITCH))[q] = vh;
            ((uint4*)(su + AL_OFF + o * APITCH))[q] = vl;
        }
        // ---- stage B row-major: 64 c-rows x 8 uint4 (64 p), hi+lo ---------
        #pragma unroll
        for (int f = tid; f < 512; f += 256) {
            int c = f >> 3, q = f & 7;
            const uint4* gh = (const uint4*)(Xh + (size_t)(kb * 64 + c) * 4608 + (p0 >> 1));
            const uint4* gl = (const uint4*)(Xl + (size_t)(kb * 64 + c) * 4608 + (p0 >> 1));
            ((uint4*)(su + BH_OFF + c * BPITCH))[q] = gh[q];
            ((uint4*)(su + BL_OFF + c * BPITCH))[q] = gl[q];
        }
        __syncthreads();

        // ---- compute: 4 k-steps of 16 -------------------------------------
        #pragma unroll 1
        for (int ks = 0; ks < 4; ks++) {
            const int k0w = ks * 8;
            uint32_t bh[2][2], bl[2][2];
            asm volatile(
                "ldmatrix.sync.aligned.m8n8.x4.trans.shared.b16 "
                "{%0,%1,%2,%3}, [%4];"
                : "=r"(bh[0][0]), "=r"(bh[0][1]), "=r"(bh[1][0]), "=r"(bh[1][1])
                : "r"(baddr_h + ks * 2304));
            asm volatile(
                "ldmatrix.sync.aligned.m8n8.x4.trans.shared.b16 "
                "{%0,%1,%2,%3}, [%4];"
                : "=r"(bl[0][0]), "=r"(bl[0][1]), "=r"(bl[1][0]), "=r"(bl[1][1])
                : "r"(baddr_l + ks * 2304));
            #pragma unroll
            for (int mi = 0; mi < 4; mi++) {
                int row = mw * 64 + mi * 16 + gq;
                int base = AH_OFF + row * APITCH + k0w + l4;
                uint32_t ah[4], al[4];
                ah[0] = su[base];
                ah[1] = su[base + 8 * APITCH];
                ah[2] = su[base + 4];
                ah[3] = su[base + 8 * APITCH + 4];
                al[0] = su[base + AL_OFF];
                al[1] = su[base + AL_OFF + 8 * APITCH];
                al[2] = su[base + AL_OFF + 4];
                al[3] = su[base + AL_OFF + 8 * APITCH + 4];
                #pragma unroll
                for (int ni = 0; ni < 2; ni++) {
                    mma16816(acc[mi][ni], ah, bh[ni]);
                    mma16816(acc[mi][ni], ah, bl[ni]);
                    mma16816(acc[mi][ni], al, bh[ni]);
                }
            }
        }
        __syncthreads();
    }

    // ---- epilogue --------------------------------------------------------
    if (MODE == 1) {
        #pragma unroll
        for (int mi = 0; mi < 4; mi++) {
            int o = o0 + mw * 64 + mi * 16 + gq;
            float b0 = bias[o], b1 = bias[o + 8];
            #pragma unroll
            for (int ni = 0; ni < 2; ni++) {
                int p = p0 + nw * 16 + ni * 8 + l4 * 2;
                float2 v0 = { acc[mi][ni][0] + b0, acc[mi][ni][1] + b0 };
                float2 v1 = { acc[mi][ni][2] + b1, acc[mi][ni][3] + b1 };
                *(float2*)(out + (size_t)o * HW + p)       = v0;
                *(float2*)(out + (size_t)(o + 8) * HW + p) = v1;
            }
        }
    } else {
        // row class (o mod 8) == gq for every acc this thread holds
        float* red = (float*)su;                 // 8 x 64
        for (int t = tid; t < 512; t += 256) red[t] = -INFINITY;
        __syncthreads();
        float bo[4][2];
        #pragma unroll
        for (int mi = 0; mi < 4; mi++) {
            int o = o0 + mw * 64 + mi * 16 + gq;
            bo[mi][0] = bias[o];
            bo[mi][1] = bias[o + 8];
        }
        #pragma unroll
        for (int ni = 0; ni < 2; ni++) {
            #pragma unroll
            for (int l = 0; l < 2; l++) {
                int col = nw * 16 + ni * 8 + l4 * 2 + l;
                float m = -INFINITY;
                #pragma unroll
                for (int mi = 0; mi < 4; mi++) {
                    m = fmaxf(m, acc[mi][ni][l]     + bo[mi][0]);
                    m = fmaxf(m, acc[mi][ni][2 + l] + bo[mi][1]);
                }
                atomicMaxFloat(&red[gq * 64 + col], m);
            }
        }
        __syncthreads();
        for (int t = tid; t < 512; t += 256) {
            int cls = t >> 6, col = t & 63;
            unsigned idx = ((unsigned)cls * 9216u + (unsigned)(p0 + col)) % 24576u;
            atomicMaxFloat(&g_FQM[idx], red[t]);
        }
    }
}

// ---------------------------------------------------------------------------
// out[e] *= (1 + g_FQM[e % 24576]), float4.
__global__ __launch_bounds__(256) void mask_epilogue(float* __restrict__ out) {
    unsigned v = blockIdx.x * 256u + threadIdx.x;
    unsigned idx = (v * 4u) % 24576u;
    float4 o = ((float4*)out)[v];
    float4 m = *(const float4*)&g_FQM[idx];
    o.x *= (1.0f + m.x);
    o.y *= (1.0f + m.y);
    o.z *= (1.0f + m.z);
    o.w *= (1.0f + m.w);
    ((float4*)out)[v] = o;
}

// ---------------------------------------------------------------------------
extern "C" void kernel_launch(void* const* d_in, const int* in_sizes, int n_in,
                              void* d_out, int out_size) {
    const float* fuse = (const float*)d_in[0];
    const float* Wq   = (const float*)d_in[1];
    const float* bq   = (const float*)d_in[2];
    // d_in[3] (Wk), d_in[4] (bk): dead code — softmax over batch axis of size 1
    const float* Wv   = (const float*)d_in[5];
    const float* bv   = (const float*)d_in[6];
    float* out = (float*)d_out;

    cudaFuncSetAttribute(gemm_mma<0>,
        cudaFuncAttributeMaxDynamicSharedMemorySize, SMEM_U32 * 4);
    cudaFuncSetAttribute(gemm_mma<1>,
        cudaFuncAttributeMaxDynamicSharedMemorySize, SMEM_U32 * 4);

    static cudaStream_t s1 = nullptr;
    static cudaEvent_t evRoot = nullptr, evT = nullptr;
    if (s1 == nullptr) {
        cudaStreamCreateWithFlags(&s1, cudaStreamNonBlocking);
        cudaEventCreateWithFlags(&evRoot, cudaEventDisableTiming);
        cudaEventCreateWithFlags(&evT, cudaEventDisableTiming);
    }

    // Side: freq (writes g_FQh/l + inits g_FQM) — the whole Q-mask prefix.
    cudaEventRecord(evRoot, 0);
    cudaStreamWaitEvent(s1, evRoot, 0);
    freq_kernel<<<C_DIM, 512, 0, s1>>>(fuse);
    cudaEventRecord(evT, s1);

    // Main: convert -> V-GEMM (overlaps freq) -> join -> Q-GEMM -> mask.
    convert_kernel<<<(NPIX/4 + 32768) / 256, 256>>>(fuse, Wq, Wv);
    gemm_mma<1><<<dim3(144, 2), 256, SMEM_U32 * 4>>>(bv, out);
    cudaStreamWaitEvent(0, evT, 0);
    gemm_mma<0><<<dim3(144, 2), 256, SMEM_U32 * 4>>>(bq, nullptr);
    mask_epilogue<<<NPIX / 4 / 256, 256>>>(out);
}